// round 16
// baseline (speedup 1.0000x reference)
#include <cuda_runtime.h>
#include <cuda_bf16.h>
#include <math.h>
#include <stdint.h>

#define BB 4
#define NN 4096
#define KK 16
#define DIN 64
#define DT 128
#define NPTS (BB*NN)

// ---- scratch (no allocs allowed) ----
__device__ __nv_bfloat16 g_q [NPTS*DT];
__device__ __nv_bfloat16 g_kf[NPTS*DT];
__device__ __nv_bfloat16 g_vf[NPTS*DT];
__device__ float g_res[NPTS*DT];
__device__ int   g_knn[NPTS*KK];
// pre-swizzled bf16 HI weight images: 0=d2,1=g1,2=g2(prescaled),3=wq,4=wk,5=wv, then fc1
__device__ __nv_bfloat16 g_wpre[6*DT*DT + DIN*DT];

#define SCALE_SM 0.08838834764831845f

__device__ __forceinline__ uint32_t smem_u32(const void* p) {
    uint32_t a;
    asm("{ .reg .u64 t; cvta.to.shared.u64 t, %1; cvt.u32.u64 %0, t; }" : "=r"(a) : "l"(p));
    return a;
}
__device__ __forceinline__ uint32_t swzoff(int r, int cb) {
    return (uint32_t)(r*256 + (cb ^ ((r & 7) << 4)));
}
__device__ __forceinline__ void ldsm4(uint32_t* r, uint32_t addr) {
    asm volatile("ldmatrix.sync.aligned.m8n8.x4.shared.b16 {%0,%1,%2,%3}, [%4];"
        : "=r"(r[0]), "=r"(r[1]), "=r"(r[2]), "=r"(r[3]) : "r"(addr));
}
__device__ __forceinline__ void ldsm4t(uint32_t* r, uint32_t addr) {
    asm volatile("ldmatrix.sync.aligned.m8n8.x4.trans.shared.b16 {%0,%1,%2,%3}, [%4];"
        : "=r"(r[0]), "=r"(r[1]), "=r"(r[2]), "=r"(r[3]) : "r"(addr));
}
__device__ __forceinline__ void mma_bf16(float* d, const uint32_t* a, const uint32_t* b) {
    asm volatile("mma.sync.aligned.m16n8k16.row.col.f32.bf16.bf16.f32 "
        "{%0,%1,%2,%3}, {%4,%5,%6,%7}, {%8,%9}, {%0,%1,%2,%3};"
        : "+f"(d[0]), "+f"(d[1]), "+f"(d[2]), "+f"(d[3])
        : "r"(a[0]), "r"(a[1]), "r"(a[2]), "r"(a[3]), "r"(b[0]), "r"(b[1]));
}
__device__ __forceinline__ uint32_t cvt2(float f0, float f1) {
    __nv_bfloat162 h = __floats2bfloat162_rn(f0, f1);
    return *(uint32_t*)&h;
}
__device__ __forceinline__ float2 unp2(uint32_t u) {
    __nv_bfloat162 h = *(__nv_bfloat162*)&u;
    return __bfloat1622float2(h);
}

// =============================== KNN (R13 config: 2 chunks, 256 CTAs x 128thr) ===============================
__global__ __launch_bounds__(128, 2) void knn_kernel(const float* __restrict__ pos) {
    extern __shared__ char ksm[];
    float4* sp = (float4*)ksm;                  // 64KB
    float2* md = (float2*)(ksm + NN*16);        // 16KB
    int t = threadIdx.x;
    int b = blockIdx.x >> 6;
    int nbase = (blockIdx.x & 63) * 64;
    const float* pb = pos + (size_t)b * NN * 3;
    for (int m = t; m < NN; m += 128) {
        float x = pb[m*3+0], y = pb[m*3+1], z = pb[m*3+2];
        sp[m] = make_float4(x, y, z, x*x + y*y + z*z);
    }
    __syncthreads();
    int q = t & 63, c = t >> 6;
    float4 qp = sp[nbase + q];
    float bd[KK]; int bi[KK];
    #pragma unroll
    for (int i = 0; i < KK; i++) { bd[i] = 3.4e38f; bi[i] = 0x7fffffff; }
    int mbase = c * (NN/2);
    for (int m0 = 0; m0 < NN/2; m0 += 8) {
        float dch[8];
        #pragma unroll
        for (int u = 0; u < 8; u++) {
            float4 p = sp[mbase + m0 + u];
            dch[u] = qp.w + p.w - 2.0f*(qp.x*p.x + qp.y*p.y + qp.z*p.z);
        }
        #pragma unroll
        for (int u = 0; u < 8; u++) {
            float d = dch[u];
            int m = mbase + m0 + u;
            if (d < bd[KK-1]) {
                #pragma unroll
                for (int j = KK-1; j >= 1; j--) {
                    if (bd[j] > d) {
                        bool sh = bd[j-1] > d;
                        bd[j] = sh ? bd[j-1] : d;
                        bi[j] = sh ? bi[j-1] : m;
                    }
                }
                if (bd[0] > d) { bd[0] = d; bi[0] = m; }
            }
        }
    }
    float2* row = md + q*32 + c*16;
    #pragma unroll
    for (int i = 0; i < KK; i++) row[i] = make_float2(bd[i], __int_as_float(bi[i]));
    __syncthreads();
    if (t < 64) {
        const float2* r2 = md + t*32;
        int h0 = 0, h1 = 16;
        int gp = b*NN + nbase + t;
        #pragma unroll
        for (int j = 0; j < KK; j++) {
            float2 a = r2[h0 < 16 ? h0 : 15];
            float2 bv = r2[h1 < 32 ? h1 : 31];
            int ai = __float_as_int(a.y), bvi = __float_as_int(bv.y);
            bool pick0;
            if (h0 >= 16) pick0 = false;
            else if (h1 >= 32) pick0 = true;
            else pick0 = (a.x < bv.x) || (a.x == bv.x && ai < bvi);
            int idx = pick0 ? ai : bvi;
            if (pick0) h0++; else h1++;
            g_knn[gp*KK + j] = b*NN + idx;
        }
    }
}

// =============================== weight prep (hi only; g2 prescaled; 7th = fc1) ===============================
__global__ void wprep_kernel(const float* __restrict__ d2_w,
                             const float* __restrict__ g1_w,
                             const float* __restrict__ g2_w,
                             const float* __restrict__ wq,
                             const float* __restrict__ wk,
                             const float* __restrict__ wv,
                             const float* __restrict__ fc1_w) {
    int s = blockIdx.x;
    const float* W = (s == 0) ? d2_w : (s == 1) ? g1_w : (s == 2) ? g2_w
                    : (s == 3) ? wq : (s == 4) ? wk : (s == 5) ? wv : fc1_w;
    int total = (s == 6) ? DIN*DT : DT*DT;
    float sc = (s == 2) ? SCALE_SM : 1.0f;
    for (int idx = threadIdx.x; idx < total; idx += blockDim.x) {
        int k = idx / DT, n = idx % DT;
        uint32_t b = swzoff(k, n*2);
        g_wpre[s*DT*DT + (b >> 1)] = __float2bfloat16(W[idx] * sc);
    }
}

// =============================== qkv (fused h), 512 thr = 2 parallel halves ===============================
constexpr int QS_W   = 0;             // 3 x 32KB (wq,wk,wv hi)
constexpr int QS_WF  = 98304;         // fc1 image 16KB
constexpr int QS_AH  = 114688;        // 2 x 8KB h images
constexpr int QS_X   = 131072;        // 2 x 8KB x images
constexpr int QS_TOTAL = 147456;

__global__ __launch_bounds__(512, 1) void qkv_mma_kernel(const float* __restrict__ x,
                                                         const float* __restrict__ fc1_b) {
    extern __shared__ char sm[];
    uint32_t sb = smem_u32(sm);
    int t = threadIdx.x;
    int half = t >> 8, u = t & 255;
    int lane = u & 31, w8 = u >> 5;
    {
        const float4* src = (const float4*)g_wpre;
        float4* dst = (float4*)(sm + QS_W);
        for (int i = t; i < 3*2048; i += 512) dst[i] = src[3*2048 + i];
        float4* dwf = (float4*)(sm + QS_WF);
        for (int i = t; i < 1024; i += 512) dwf[i] = src[6*2048 + i];
    }
    uint32_t ah = sb + QS_AH + half*8192;
    uint32_t xh = sb + QS_X  + half*8192;
    uint32_t wf = sb + QS_WF;
    int r0 = lane >> 2, c2 = 2*(lane & 3);
    int tr = lane & 15, th = lane >> 4;
    int rowA = u >> 3, cbA = (u & 7) * 8;
    int rowbase = blockIdx.x*64 + half*32;

    __syncthreads();
    {
        const float* xr = x + (size_t)(rowbase + rowA)*DIN + cbA;
        uint32_t xv[4];
        #pragma unroll
        for (int i = 0; i < 4; i++) xv[i] = cvt2(xr[2*i], xr[2*i+1]);
        *(uint4*)(sm + QS_X + half*8192 + swzoff(rowA, cbA*2)) = make_uint4(xv[0],xv[1],xv[2],xv[3]);
    }
    __syncthreads();
    {
        float hc0[2][4], hc1[2][4];
        #pragma unroll
        for (int n = 0; n < 2; n++)
            #pragma unroll
            for (int j = 0; j < 4; j++) { hc0[n][j] = 0.f; hc1[n][j] = 0.f; }
        #pragma unroll
        for (int ks = 0; ks < 4; ks++) {
            uint32_t a0[4], a1[4], bh[4];
            ldsm4(a0, xh + swzoff(tr,      (ks*16 + th*8)*2));
            ldsm4(a1, xh + swzoff(tr + 16, (ks*16 + th*8)*2));
            ldsm4t(bh, wf + swzoff(ks*16 + tr, (w8*16 + th*8)*2));
            mma_bf16(hc0[0], a0, bh+0); mma_bf16(hc0[1], a0, bh+2);
            mma_bf16(hc1[0], a1, bh+0); mma_bf16(hc1[1], a1, bh+2);
        }
        #pragma unroll
        for (int nt = 0; nt < 2; nt++) {
            int col = w8*16 + nt*8 + c2;
            float2 bb = *(const float2*)(fc1_b + col);
            char* base = sm + QS_AH + half*8192;
            *(uint32_t*)(base + swzoff(r0,      col*2)) = cvt2(hc0[nt][0]+bb.x, hc0[nt][1]+bb.y);
            *(uint32_t*)(base + swzoff(r0 + 8,  col*2)) = cvt2(hc0[nt][2]+bb.x, hc0[nt][3]+bb.y);
            *(uint32_t*)(base + swzoff(r0 + 16, col*2)) = cvt2(hc1[nt][0]+bb.x, hc1[nt][1]+bb.y);
            *(uint32_t*)(base + swzoff(r0 + 24, col*2)) = cvt2(hc1[nt][2]+bb.x, hc1[nt][3]+bb.y);
        }
    }
    __syncthreads();
    float acc0[6][4], acc1[6][4];
    #pragma unroll
    for (int n = 0; n < 6; n++)
        #pragma unroll
        for (int j = 0; j < 4; j++) { acc0[n][j] = 0.f; acc1[n][j] = 0.f; }
    #pragma unroll
    for (int ks = 0; ks < 8; ks++) {
        uint32_t aoff0 = swzoff(tr,      (ks*16 + th*8)*2);
        uint32_t aoff1 = swzoff(tr + 16, (ks*16 + th*8)*2);
        uint32_t ah0[4], ah1[4];
        ldsm4(ah0, ah + aoff0);
        ldsm4(ah1, ah + aoff1);
        #pragma unroll
        for (int gg = 0; gg < 3; gg++) {
            int c0 = w8*48 + gg*16;
            int img = c0 >> 7, coff = c0 & 127;
            uint32_t wh = sb + QS_W + img*32768;
            uint32_t boff = swzoff(ks*16 + tr, (coff + th*8)*2);
            uint32_t bh[4];
            ldsm4t(bh, wh + boff);
            mma_bf16(acc0[2*gg], ah0, bh+0); mma_bf16(acc0[2*gg+1], ah0, bh+2);
            mma_bf16(acc1[2*gg], ah1, bh+0); mma_bf16(acc1[2*gg+1], ah1, bh+2);
        }
    }
    #pragma unroll
    for (int nt = 0; nt < 6; nt++) {
        int gc = w8*48 + nt*8 + c2;
        int img = gc >> 7, col = gc & 127;
        __nv_bfloat16* dst = (img == 0) ? g_q : (img == 1) ? g_kf : g_vf;
        *(uint32_t*)(dst + (size_t)(rowbase + r0     )*DT + col) = cvt2(acc0[nt][0], acc0[nt][1]);
        *(uint32_t*)(dst + (size_t)(rowbase + r0 + 8 )*DT + col) = cvt2(acc0[nt][2], acc0[nt][3]);
        *(uint32_t*)(dst + (size_t)(rowbase + r0 + 16)*DT + col) = cvt2(acc1[nt][0], acc1[nt][1]);
        *(uint32_t*)(dst + (size_t)(rowbase + r0 + 24)*DT + col) = cvt2(acc1[nt][2], acc1[nt][3]);
    }
}

// =============================== mega: warp-per-point + smem attn staging ===============================
constexpr int MW_W    = 0;            // 96KB (d2,g1,g2 hi)
constexpr int MW_D1W  = 98304;
constexpr int MW_D1B  = 99840;
constexpr int MW_D2B  = 100352;
constexpr int MW_G1B  = 100864;
constexpr int MW_G2B  = 101376;
constexpr int MW_ABUF = 101888;       // 8 warps x 16x132 f32 = 67584 B
constexpr int ABUF_STRIDE = 132;      // floats per row (pad: bank spread)
constexpr int MW_TOTAL= MW_ABUF + 8*16*ABUF_STRIDE*4;   // 169472

__device__ __forceinline__ void cvtA(const float (*c)[4], uint32_t (*ahh)[4]) {
    #pragma unroll
    for (int ks = 0; ks < 8; ks++) {
        ahh[ks][0] = cvt2(c[2*ks][0],   c[2*ks][1]);
        ahh[ks][1] = cvt2(c[2*ks][2],   c[2*ks][3]);
        ahh[ks][2] = cvt2(c[2*ks+1][0], c[2*ks+1][1]);
        ahh[ks][3] = cvt2(c[2*ks+1][2], c[2*ks+1][3]);
    }
}
__device__ __forceinline__ void wgemm(float (*c)[4], const uint32_t (*ahh)[4],
        uint32_t wh, int tr, int th) {
    #pragma unroll
    for (int ks = 0; ks < 8; ks++) {
        #pragma unroll
        for (int n16 = 0; n16 < 8; n16++) {
            uint32_t boff = swzoff(ks*16 + tr, (n16*16 + th*8)*2);
            uint32_t bh[4];
            ldsm4t(bh, wh + boff);
            mma_bf16(c[2*n16],   ahh[ks], bh+0);
            mma_bf16(c[2*n16+1], ahh[ks], bh+2);
        }
    }
}

__global__ __launch_bounds__(256, 1) void mega_warp_kernel(const float* __restrict__ pos,
        const float* __restrict__ d1_w, const float* __restrict__ d1_b,
        const float* __restrict__ d2_b, const float* __restrict__ g1_b,
        const float* __restrict__ g2_b,
        float* __restrict__ attn_out, int write_attn)
{
    extern __shared__ char sm[];
    float* smf = (float*)sm;
    uint32_t sb = smem_u32(sm);
    int t = threadIdx.x, lane = t & 31, warp = t >> 5;
    {
        const float4* src = (const float4*)g_wpre;
        float4* dst = (float4*)(sm + MW_W);
        for (int i = t; i < 3*2048; i += 256) dst[i] = src[i];
        for (int i = t; i < 3*DT; i += 256) smf[(MW_D1W>>2) + i] = d1_w[i];
        if (t < DT) {
            smf[(MW_D1B>>2)+t] = d1_b[t];
            smf[(MW_D2B>>2)+t] = d2_b[t];
            smf[(MW_G1B>>2)+t] = g1_b[t];
            smf[(MW_G2B>>2)+t] = g2_b[t] * SCALE_SM;
        }
    }
    __syncthreads();

    int g = lane >> 2, t2 = 2*(lane & 3);
    int tr = lane & 15, th = lane >> 4;
    uint32_t wh0 = sb + MW_W;
    uint32_t wh1 = sb + MW_W + 32768;
    uint32_t wh2 = sb + MW_W + 65536;
    float* abuf = smf + (MW_ABUF>>2) + warp*(16*ABUF_STRIDE);
    int gwarp = blockIdx.x*8 + warp;
    int nwarps = gridDim.x*8;

    int gi0 = 0, gi1 = 0;
    if (gwarp < NPTS) {
        gi0 = g_knn[gwarp*KK + g];
        gi1 = g_knn[gwarp*KK + g + 8];
    }

    for (int pt = gwarp; pt < NPTS; pt += nwarps) {
        float px = pos[pt*3+0], py = pos[pt*3+1], pz = pos[pt*3+2];
        float r0x = px - pos[gi0*3+0], r0y = py - pos[gi0*3+1], r0z = pz - pos[gi0*3+2];
        float r1x = px - pos[gi1*3+0], r1y = py - pos[gi1*3+1], r1z = pz - pos[gi1*3+2];

        uint32_t qf[16], k0f[16], k1f[16];
        #pragma unroll
        for (int j = 0; j < 16; j++) {
            int col = 8*j + t2;
            qf[j]  = *(const uint32_t*)(g_q  + (size_t)pt*DT + col);
            k0f[j] = *(const uint32_t*)(g_kf + (size_t)gi0*DT + col);
            k1f[j] = *(const uint32_t*)(g_kf + (size_t)gi1*DT + col);
        }

        float c[16][4];
        uint32_t ahh[8][4];

        // ---- T stage ----
        #pragma unroll
        for (int j = 0; j < 16; j++) {
            int col = 8*j + t2;
            float2 w0 = *(const float2*)(smf + (MW_D1W>>2) + col);
            float2 w1 = *(const float2*)(smf + (MW_D1W>>2) + DT + col);
            float2 w2 = *(const float2*)(smf + (MW_D1W>>2) + 2*DT + col);
            float2 bb = *(const float2*)(smf + (MW_D1B>>2) + col);
            c[j][0] = fmaxf(bb.x + r0x*w0.x + r0y*w1.x + r0z*w2.x, 0.f);
            c[j][1] = fmaxf(bb.y + r0x*w0.y + r0y*w1.y + r0z*w2.y, 0.f);
            c[j][2] = fmaxf(bb.x + r1x*w0.x + r1y*w1.x + r1z*w2.x, 0.f);
            c[j][3] = fmaxf(bb.y + r1x*w0.y + r1y*w1.y + r1z*w2.y, 0.f);
        }
        cvtA(c, ahh);

        // ---- GEMM1: pe ----
        #pragma unroll
        for (int j = 0; j < 16; j++) { c[j][0]=0.f; c[j][1]=0.f; c[j][2]=0.f; c[j][3]=0.f; }
        wgemm(c, ahh, wh0, tr, th);
        uint32_t peb0[16], peb1[16];
        #pragma unroll
        for (int j = 0; j < 16; j++) {
            float2 bb = *(const float2*)(smf + (MW_D2B>>2) + 8*j + t2);
            peb0[j] = cvt2(c[j][0] + bb.x, c[j][1] + bb.y);
            peb1[j] = cvt2(c[j][2] + bb.x, c[j][3] + bb.y);
        }

        // ---- a_in ----
        #pragma unroll
        for (int j = 0; j < 16; j++) {
            float2 p0 = unp2(peb0[j]), p1 = unp2(peb1[j]);
            float2 qv = unp2(qf[j]);
            float2 k0 = unp2(k0f[j]);
            float2 k1 = unp2(k1f[j]);
            c[j][0] = qv.x - k0.x + p0.x;
            c[j][1] = qv.y - k0.y + p0.y;
            c[j][2] = qv.x - k1.x + p1.x;
            c[j][3] = qv.y - k1.y + p1.y;
        }
        cvtA(c, ahh);

        uint32_t v0f[16], v1f[16];
        #pragma unroll
        for (int j = 0; j < 16; j++) {
            int col = 8*j + t2;
            v0f[j] = *(const uint32_t*)(g_vf + (size_t)gi0*DT + col);
            v1f[j] = *(const uint32_t*)(g_vf + (size_t)gi1*DT + col);
        }

        // ---- GEMM2: u ----
        #pragma unroll
        for (int j = 0; j < 16; j++) { c[j][0]=0.f; c[j][1]=0.f; c[j][2]=0.f; c[j][3]=0.f; }
        wgemm(c, ahh, wh1, tr, th);
        #pragma unroll
        for (int j = 0; j < 16; j++) {
            float2 bb = *(const float2*)(smf + (MW_G1B>>2) + 8*j + t2);
            c[j][0] = fmaxf(c[j][0] + bb.x, 0.f); c[j][1] = fmaxf(c[j][1] + bb.y, 0.f);
            c[j][2] = fmaxf(c[j][2] + bb.x, 0.f); c[j][3] = fmaxf(c[j][3] + bb.y, 0.f);
        }
        cvtA(c, ahh);

        // ---- GEMM3 ----
        #pragma unroll
        for (int j = 0; j < 16; j++) { c[j][0]=0.f; c[j][1]=0.f; c[j][2]=0.f; c[j][3]=0.f; }
        wgemm(c, ahh, wh2, tr, th);

        int npt = pt + nwarps;
        int ngi0 = gi0, ngi1 = gi1;
        if (npt < NPTS) {
            ngi0 = g_knn[npt*KK + g];
            ngi1 = g_knn[npt*KK + g + 8];
        }

        // ---- softmax + res; attn -> smem staging ----
        #pragma unroll
        for (int j = 0; j < 16; j++) {
            int col = 8*j + t2;
            float2 bb = *(const float2*)(smf + (MW_G2B>>2) + col);
            float e00 = __expf(c[j][0] + bb.x);
            float e01 = __expf(c[j][1] + bb.y);
            float e10 = __expf(c[j][2] + bb.x);
            float e11 = __expf(c[j][3] + bb.y);
            float s0 = e00 + e10, s1 = e01 + e11;
            #pragma unroll
            for (int o = 4; o <= 16; o <<= 1) {
                s0 += __shfl_xor_sync(0xffffffffu, s0, o);
                s1 += __shfl_xor_sync(0xffffffffu, s1, o);
            }
            float i0 = 1.0f / s0, i1 = 1.0f / s1;
            float a00 = e00*i0, a10 = e10*i0, a01 = e01*i1, a11 = e11*i1;
            *(float2*)(abuf + g*ABUF_STRIDE + col)       = make_float2(a00, a01);
            *(float2*)(abuf + (g+8)*ABUF_STRIDE + col)   = make_float2(a10, a11);
            float2 p0 = unp2(peb0[j]), p1 = unp2(peb1[j]);
            float2 v0 = unp2(v0f[j]), v1 = unp2(v1f[j]);
            float t0 = a00*(v0.x + p0.x) + a10*(v1.x + p1.x);
            float t1 = a01*(v0.y + p0.y) + a11*(v1.y + p1.y);
            #pragma unroll
            for (int o = 4; o <= 16; o <<= 1) {
                t0 += __shfl_xor_sync(0xffffffffu, t0, o);
                t1 += __shfl_xor_sync(0xffffffffu, t1, o);
            }
            if (lane < 4) *(float2*)(g_res + (size_t)pt*DT + col) = make_float2(t0, t1);
        }
        __syncwarp();
        // coalesced attn write-out: 16 rows x 128 f32, one LDS.128+STG.128 per row per lane
        if (write_attn) {
            float* dst = attn_out + (size_t)pt*KK*DT;
            #pragma unroll
            for (int r = 0; r < 16; r++) {
                float4 v = *(const float4*)(abuf + r*ABUF_STRIDE + lane*4);
                *(float4*)(dst + r*DT + lane*4) = v;
            }
        }
        __syncwarp();
        gi0 = ngi0; gi1 = ngi1;
    }
}

// =============================== out = res@fc2_w + b + x (tiled) ===============================
__global__ __launch_bounds__(128, 1) void out_kernel(const float* __restrict__ x,
        const float* __restrict__ fc2_w, const float* __restrict__ fc2_b, float* __restrict__ out) {
    __shared__ float ws[DT*DIN];
    __shared__ float rbuf[16*DT];
    int t = threadIdx.x;
    int base = blockIdx.x * 16;
    {
        float4* ws4=(float4*)ws; const float4* w4=(const float4*)fc2_w;
        for (int i=t; i<DT*DIN/4; i+=128) ws4[i]=w4[i];
        const float4* rsrc = (const float4*)(g_res + (size_t)base*DT);
        float4* rb4=(float4*)rbuf;
        for (int i=t; i<16*DT/4; i+=128) rb4[i]=rsrc[i];
    }
    __syncthreads();
    int c4 = (t & 15) * 4;
    int r2 = (t >> 4) * 2;
    float4 bias = *(const float4*)(fc2_b + c4);
    float a0x=bias.x, a0y=bias.y, a0z=bias.z, a0w=bias.w;
    float a1x=bias.x, a1y=bias.y, a1z=bias.z, a1w=bias.w;
    const float* rrow0 = rbuf + r2*DT;
    const float* rrow1 = rbuf + (r2+1)*DT;
    #pragma unroll 4
    for (int i = 0; i < DT; i++) {
        float4 w = *(const float4*)(ws + i*DIN + c4);
        float ra = rrow0[i], rb = rrow1[i];
        a0x += ra*w.x; a0y += ra*w.y; a0z += ra*w.z; a0w += ra*w.w;
        a1x += rb*w.x; a1y += rb*w.y; a1z += rb*w.z; a1w += rb*w.w;
    }
    {
        float4 x0 = *(const float4*)(x + (size_t)(base+r2)*DIN + c4);
        float4 x1 = *(const float4*)(x + (size_t)(base+r2+1)*DIN + c4);
        *(float4*)(out + (size_t)(base+r2)*DIN + c4)   = make_float4(a0x+x0.x, a0y+x0.y, a0z+x0.z, a0w+x0.w);
        *(float4*)(out + (size_t)(base+r2+1)*DIN + c4) = make_float4(a1x+x1.x, a1y+x1.y, a1z+x1.z, a1w+x1.w);
    }
}

// =============================== launch ===============================
extern "C" void kernel_launch(void* const* d_in, const int* in_sizes, int n_in,
                              void* d_out, int out_size) {
    const float* x     = (const float*)d_in[0];
    const float* pos   = (const float*)d_in[1];
    const float* fc1_w = (const float*)d_in[2];
    const float* fc1_b = (const float*)d_in[3];
    const float* fc2_w = (const float*)d_in[4];
    const float* fc2_b = (const float*)d_in[5];
    const float* d1_w  = (const float*)d_in[6];
    const float* d1_b  = (const float*)d_in[7];
    const float* d2_w  = (const float*)d_in[8];
    const float* d2_b  = (const float*)d_in[9];
    const float* g1_w  = (const float*)d_in[10];
    const float* g1_b  = (const float*)d_in[11];
    const float* g2_w  = (const float*)d_in[12];
    const float* g2_b  = (const float*)d_in[13];
    const float* wq    = (const float*)d_in[14];
    const float* wk    = (const float*)d_in[15];
    const float* wv    = (const float*)d_in[16];
    float* out = (float*)d_out;
    int write_attn = (out_size >= NPTS*DIN + NPTS*KK*DT) ? 1 : 0;
    float* attn_out = out + (size_t)NPTS*DIN;

    int knn_smem = NN*16 + 64*32*8;
    cudaFuncSetAttribute(knn_kernel,       cudaFuncAttributeMaxDynamicSharedMemorySize, knn_smem);
    cudaFuncSetAttribute(qkv_mma_kernel,   cudaFuncAttributeMaxDynamicSharedMemorySize, QS_TOTAL);
    cudaFuncSetAttribute(mega_warp_kernel, cudaFuncAttributeMaxDynamicSharedMemorySize, MW_TOTAL);

    knn_kernel<<<BB*64, 128, knn_smem>>>(pos);
    wprep_kernel<<<7, 256>>>(d2_w, g1_w, g2_w, wq, wk, wv, fc1_w);
    qkv_mma_kernel<<<NPTS/64, 512, QS_TOTAL>>>(x, fc1_b);
    mega_warp_kernel<<<148, 256, MW_TOTAL>>>(pos, d1_w, d1_b, d2_b, g1_b, g2_b,
                                             attn_out, write_attn);
    out_kernel<<<NPTS/16, 128>>>(x, fc2_w, fc2_b, out);
}

// round 17
// speedup vs baseline: 1.0379x; 1.0379x over previous
#include <cuda_runtime.h>
#include <cuda_bf16.h>
#include <math.h>
#include <stdint.h>

#define BB 4
#define NN 4096
#define KK 16
#define DIN 64
#define DT 128
#define NPTS (BB*NN)

// ---- scratch (no allocs allowed) ----
__device__ __nv_bfloat16 g_q [NPTS*DT];
__device__ __nv_bfloat16 g_kf[NPTS*DT];
__device__ __nv_bfloat16 g_vf[NPTS*DT];
__device__ float g_res[NPTS*DT];
__device__ int   g_knn[NPTS*KK];
// pre-swizzled bf16 HI weight images: 0=d2,1=g1,2=g2(prescaled),3=wq,4=wk,5=wv, then fc1
__device__ __nv_bfloat16 g_wpre[6*DT*DT + DIN*DT];

#define SCALE_SM 0.08838834764831845f

__device__ __forceinline__ uint32_t smem_u32(const void* p) {
    uint32_t a;
    asm("{ .reg .u64 t; cvta.to.shared.u64 t, %1; cvt.u32.u64 %0, t; }" : "=r"(a) : "l"(p));
    return a;
}
__device__ __forceinline__ uint32_t swzoff(int r, int cb) {
    return (uint32_t)(r*256 + (cb ^ ((r & 7) << 4)));
}
__device__ __forceinline__ void ldsm4(uint32_t* r, uint32_t addr) {
    asm volatile("ldmatrix.sync.aligned.m8n8.x4.shared.b16 {%0,%1,%2,%3}, [%4];"
        : "=r"(r[0]), "=r"(r[1]), "=r"(r[2]), "=r"(r[3]) : "r"(addr));
}
__device__ __forceinline__ void ldsm4t(uint32_t* r, uint32_t addr) {
    asm volatile("ldmatrix.sync.aligned.m8n8.x4.trans.shared.b16 {%0,%1,%2,%3}, [%4];"
        : "=r"(r[0]), "=r"(r[1]), "=r"(r[2]), "=r"(r[3]) : "r"(addr));
}
__device__ __forceinline__ void mma_bf16(float* d, const uint32_t* a, const uint32_t* b) {
    asm volatile("mma.sync.aligned.m16n8k16.row.col.f32.bf16.bf16.f32 "
        "{%0,%1,%2,%3}, {%4,%5,%6,%7}, {%8,%9}, {%0,%1,%2,%3};"
        : "+f"(d[0]), "+f"(d[1]), "+f"(d[2]), "+f"(d[3])
        : "r"(a[0]), "r"(a[1]), "r"(a[2]), "r"(a[3]), "r"(b[0]), "r"(b[1]));
}
__device__ __forceinline__ uint32_t cvt2(float f0, float f1) {
    __nv_bfloat162 h = __floats2bfloat162_rn(f0, f1);
    return *(uint32_t*)&h;
}
__device__ __forceinline__ float2 unp2(uint32_t u) {
    __nv_bfloat162 h = *(__nv_bfloat162*)&u;
    return __bfloat1622float2(h);
}

// =============================== KNN (R13 + candidate prefetch pipeline) ===============================
__global__ __launch_bounds__(128, 2) void knn_kernel(const float* __restrict__ pos) {
    extern __shared__ char ksm[];
    float4* sp = (float4*)ksm;                  // 64KB
    float2* md = (float2*)(ksm + NN*16);        // 16KB
    int t = threadIdx.x;
    int b = blockIdx.x >> 6;
    int nbase = (blockIdx.x & 63) * 64;
    const float* pb = pos + (size_t)b * NN * 3;
    for (int m = t; m < NN; m += 128) {
        float x = pb[m*3+0], y = pb[m*3+1], z = pb[m*3+2];
        sp[m] = make_float4(x, y, z, x*x + y*y + z*z);
    }
    __syncthreads();
    int q = t & 63, c = t >> 6;
    float4 qp = sp[nbase + q];
    float bd[KK]; int bi[KK];
    #pragma unroll
    for (int i = 0; i < KK; i++) { bd[i] = 3.4e38f; bi[i] = 0x7fffffff; }
    const int L = NN/2;                          // 2048, power of two
    int mbase = c * L;
    float4 pc[8];
    #pragma unroll
    for (int u = 0; u < 8; u++) pc[u] = sp[mbase + u];
    for (int m0 = 0; m0 < L; m0 += 8) {
        // distances for current chunk from prefetched registers
        float dch[8];
        #pragma unroll
        for (int u = 0; u < 8; u++) {
            float4 p = pc[u];
            dch[u] = qp.w + p.w - 2.0f*(qp.x*p.x + qp.y*p.y + qp.z*p.z);
        }
        // prefetch next chunk (wrapped, unconditional) -> LDS latency hides under inserts
        int nb = mbase + ((m0 + 8) & (L - 1));
        #pragma unroll
        for (int u = 0; u < 8; u++) pc[u] = sp[nb + u];
        // insert phase
        #pragma unroll
        for (int u = 0; u < 8; u++) {
            float d = dch[u];
            int m = mbase + m0 + u;
            if (d < bd[KK-1]) {
                #pragma unroll
                for (int j = KK-1; j >= 1; j--) {
                    if (bd[j] > d) {
                        bool sh = bd[j-1] > d;
                        bd[j] = sh ? bd[j-1] : d;
                        bi[j] = sh ? bi[j-1] : m;
                    }
                }
                if (bd[0] > d) { bd[0] = d; bi[0] = m; }
            }
        }
    }
    float2* row = md + q*32 + c*16;
    #pragma unroll
    for (int i = 0; i < KK; i++) row[i] = make_float2(bd[i], __int_as_float(bi[i]));
    __syncthreads();
    if (t < 64) {
        const float2* r2 = md + t*32;
        int h0 = 0, h1 = 16;
        int gp = b*NN + nbase + t;
        #pragma unroll
        for (int j = 0; j < KK; j++) {
            float2 a = r2[h0 < 16 ? h0 : 15];
            float2 bv = r2[h1 < 32 ? h1 : 31];
            int ai = __float_as_int(a.y), bvi = __float_as_int(bv.y);
            bool pick0;
            if (h0 >= 16) pick0 = false;
            else if (h1 >= 32) pick0 = true;
            else pick0 = (a.x < bv.x) || (a.x == bv.x && ai < bvi);
            int idx = pick0 ? ai : bvi;
            if (pick0) h0++; else h1++;
            g_knn[gp*KK + j] = b*NN + idx;
        }
    }
}

// =============================== weight prep (hi only; g2 prescaled; 7th = fc1) ===============================
__global__ void wprep_kernel(const float* __restrict__ d2_w,
                             const float* __restrict__ g1_w,
                             const float* __restrict__ g2_w,
                             const float* __restrict__ wq,
                             const float* __restrict__ wk,
                             const float* __restrict__ wv,
                             const float* __restrict__ fc1_w) {
    int s = blockIdx.x;
    const float* W = (s == 0) ? d2_w : (s == 1) ? g1_w : (s == 2) ? g2_w
                    : (s == 3) ? wq : (s == 4) ? wk : (s == 5) ? wv : fc1_w;
    int total = (s == 6) ? DIN*DT : DT*DT;
    float sc = (s == 2) ? SCALE_SM : 1.0f;
    for (int idx = threadIdx.x; idx < total; idx += blockDim.x) {
        int k = idx / DT, n = idx % DT;
        uint32_t b = swzoff(k, n*2);
        g_wpre[s*DT*DT + (b >> 1)] = __float2bfloat16(W[idx] * sc);
    }
}

// =============================== qkv (fused h), 512 thr = 2 parallel halves ===============================
constexpr int QS_W   = 0;
constexpr int QS_WF  = 98304;
constexpr int QS_AH  = 114688;
constexpr int QS_X   = 131072;
constexpr int QS_TOTAL = 147456;

__global__ __launch_bounds__(512, 1) void qkv_mma_kernel(const float* __restrict__ x,
                                                         const float* __restrict__ fc1_b) {
    extern __shared__ char sm[];
    uint32_t sb = smem_u32(sm);
    int t = threadIdx.x;
    int half = t >> 8, u = t & 255;
    int lane = u & 31, w8 = u >> 5;
    {
        const float4* src = (const float4*)g_wpre;
        float4* dst = (float4*)(sm + QS_W);
        for (int i = t; i < 3*2048; i += 512) dst[i] = src[3*2048 + i];
        float4* dwf = (float4*)(sm + QS_WF);
        for (int i = t; i < 1024; i += 512) dwf[i] = src[6*2048 + i];
    }
    uint32_t ah = sb + QS_AH + half*8192;
    uint32_t xh = sb + QS_X  + half*8192;
    uint32_t wf = sb + QS_WF;
    int r0 = lane >> 2, c2 = 2*(lane & 3);
    int tr = lane & 15, th = lane >> 4;
    int rowA = u >> 3, cbA = (u & 7) * 8;
    int rowbase = blockIdx.x*64 + half*32;

    __syncthreads();
    {
        const float* xr = x + (size_t)(rowbase + rowA)*DIN + cbA;
        uint32_t xv[4];
        #pragma unroll
        for (int i = 0; i < 4; i++) xv[i] = cvt2(xr[2*i], xr[2*i+1]);
        *(uint4*)(sm + QS_X + half*8192 + swzoff(rowA, cbA*2)) = make_uint4(xv[0],xv[1],xv[2],xv[3]);
    }
    __syncthreads();
    {
        float hc0[2][4], hc1[2][4];
        #pragma unroll
        for (int n = 0; n < 2; n++)
            #pragma unroll
            for (int j = 0; j < 4; j++) { hc0[n][j] = 0.f; hc1[n][j] = 0.f; }
        #pragma unroll
        for (int ks = 0; ks < 4; ks++) {
            uint32_t a0[4], a1[4], bh[4];
            ldsm4(a0, xh + swzoff(tr,      (ks*16 + th*8)*2));
            ldsm4(a1, xh + swzoff(tr + 16, (ks*16 + th*8)*2));
            ldsm4t(bh, wf + swzoff(ks*16 + tr, (w8*16 + th*8)*2));
            mma_bf16(hc0[0], a0, bh+0); mma_bf16(hc0[1], a0, bh+2);
            mma_bf16(hc1[0], a1, bh+0); mma_bf16(hc1[1], a1, bh+2);
        }
        #pragma unroll
        for (int nt = 0; nt < 2; nt++) {
            int col = w8*16 + nt*8 + c2;
            float2 bb = *(const float2*)(fc1_b + col);
            char* base = sm + QS_AH + half*8192;
            *(uint32_t*)(base + swzoff(r0,      col*2)) = cvt2(hc0[nt][0]+bb.x, hc0[nt][1]+bb.y);
            *(uint32_t*)(base + swzoff(r0 + 8,  col*2)) = cvt2(hc0[nt][2]+bb.x, hc0[nt][3]+bb.y);
            *(uint32_t*)(base + swzoff(r0 + 16, col*2)) = cvt2(hc1[nt][0]+bb.x, hc1[nt][1]+bb.y);
            *(uint32_t*)(base + swzoff(r0 + 24, col*2)) = cvt2(hc1[nt][2]+bb.x, hc1[nt][3]+bb.y);
        }
    }
    __syncthreads();
    float acc0[6][4], acc1[6][4];
    #pragma unroll
    for (int n = 0; n < 6; n++)
        #pragma unroll
        for (int j = 0; j < 4; j++) { acc0[n][j] = 0.f; acc1[n][j] = 0.f; }
    #pragma unroll
    for (int ks = 0; ks < 8; ks++) {
        uint32_t aoff0 = swzoff(tr,      (ks*16 + th*8)*2);
        uint32_t aoff1 = swzoff(tr + 16, (ks*16 + th*8)*2);
        uint32_t ah0[4], ah1[4];
        ldsm4(ah0, ah + aoff0);
        ldsm4(ah1, ah + aoff1);
        #pragma unroll
        for (int gg = 0; gg < 3; gg++) {
            int c0 = w8*48 + gg*16;
            int img = c0 >> 7, coff = c0 & 127;
            uint32_t wh = sb + QS_W + img*32768;
            uint32_t boff = swzoff(ks*16 + tr, (coff + th*8)*2);
            uint32_t bh[4];
            ldsm4t(bh, wh + boff);
            mma_bf16(acc0[2*gg], ah0, bh+0); mma_bf16(acc0[2*gg+1], ah0, bh+2);
            mma_bf16(acc1[2*gg], ah1, bh+0); mma_bf16(acc1[2*gg+1], ah1, bh+2);
        }
    }
    #pragma unroll
    for (int nt = 0; nt < 6; nt++) {
        int gc = w8*48 + nt*8 + c2;
        int img = gc >> 7, col = gc & 127;
        __nv_bfloat16* dst = (img == 0) ? g_q : (img == 1) ? g_kf : g_vf;
        *(uint32_t*)(dst + (size_t)(rowbase + r0     )*DT + col) = cvt2(acc0[nt][0], acc0[nt][1]);
        *(uint32_t*)(dst + (size_t)(rowbase + r0 + 8 )*DT + col) = cvt2(acc0[nt][2], acc0[nt][3]);
        *(uint32_t*)(dst + (size_t)(rowbase + r0 + 16)*DT + col) = cvt2(acc1[nt][0], acc1[nt][1]);
        *(uint32_t*)(dst + (size_t)(rowbase + r0 + 24)*DT + col) = cvt2(acc1[nt][2], acc1[nt][3]);
    }
}

// =============================== mega: warp-per-point (R15 exact) ===============================
constexpr int MW_W    = 0;            // 96KB (d2,g1,g2 hi)
constexpr int MW_D1W  = 98304;
constexpr int MW_D1B  = 99840;
constexpr int MW_D2B  = 100352;
constexpr int MW_G1B  = 100864;
constexpr int MW_G2B  = 101376;
constexpr int MW_TOTAL= 101888;

__device__ __forceinline__ void cvtA(const float (*c)[4], uint32_t (*ahh)[4]) {
    #pragma unroll
    for (int ks = 0; ks < 8; ks++) {
        ahh[ks][0] = cvt2(c[2*ks][0],   c[2*ks][1]);
        ahh[ks][1] = cvt2(c[2*ks][2],   c[2*ks][3]);
        ahh[ks][2] = cvt2(c[2*ks+1][0], c[2*ks+1][1]);
        ahh[ks][3] = cvt2(c[2*ks+1][2], c[2*ks+1][3]);
    }
}
__device__ __forceinline__ void wgemm(float (*c)[4], const uint32_t (*ahh)[4],
        uint32_t wh, int tr, int th) {
    #pragma unroll
    for (int ks = 0; ks < 8; ks++) {
        #pragma unroll
        for (int n16 = 0; n16 < 8; n16++) {
            uint32_t boff = swzoff(ks*16 + tr, (n16*16 + th*8)*2);
            uint32_t bh[4];
            ldsm4t(bh, wh + boff);
            mma_bf16(c[2*n16],   ahh[ks], bh+0);
            mma_bf16(c[2*n16+1], ahh[ks], bh+2);
        }
    }
}

__global__ __launch_bounds__(256, 1) void mega_warp_kernel(const float* __restrict__ pos,
        const float* __restrict__ d1_w, const float* __restrict__ d1_b,
        const float* __restrict__ d2_b, const float* __restrict__ g1_b,
        const float* __restrict__ g2_b,
        float* __restrict__ attn_out, int write_attn)
{
    extern __shared__ char sm[];
    float* smf = (float*)sm;
    uint32_t sb = smem_u32(sm);
    int t = threadIdx.x, lane = t & 31, warp = t >> 5;
    {
        const float4* src = (const float4*)g_wpre;
        float4* dst = (float4*)(sm + MW_W);
        for (int i = t; i < 3*2048; i += 256) dst[i] = src[i];
        for (int i = t; i < 3*DT; i += 256) smf[(MW_D1W>>2) + i] = d1_w[i];
        if (t < DT) {
            smf[(MW_D1B>>2)+t] = d1_b[t];
            smf[(MW_D2B>>2)+t] = d2_b[t];
            smf[(MW_G1B>>2)+t] = g1_b[t];
            smf[(MW_G2B>>2)+t] = g2_b[t] * SCALE_SM;
        }
    }
    __syncthreads();

    int g = lane >> 2, t2 = 2*(lane & 3);
    int tr = lane & 15, th = lane >> 4;
    uint32_t wh0 = sb + MW_W;
    uint32_t wh1 = sb + MW_W + 32768;
    uint32_t wh2 = sb + MW_W + 65536;
    int gwarp = blockIdx.x*8 + warp;
    int nwarps = gridDim.x*8;

    int gi0 = 0, gi1 = 0;
    if (gwarp < NPTS) {
        gi0 = g_knn[gwarp*KK + g];
        gi1 = g_knn[gwarp*KK + g + 8];
    }

    for (int pt = gwarp; pt < NPTS; pt += nwarps) {
        float px = pos[pt*3+0], py = pos[pt*3+1], pz = pos[pt*3+2];
        float r0x = px - pos[gi0*3+0], r0y = py - pos[gi0*3+1], r0z = pz - pos[gi0*3+2];
        float r1x = px - pos[gi1*3+0], r1y = py - pos[gi1*3+1], r1z = pz - pos[gi1*3+2];

        uint32_t qf[16], k0f[16], k1f[16];
        #pragma unroll
        for (int j = 0; j < 16; j++) {
            int col = 8*j + t2;
            qf[j]  = *(const uint32_t*)(g_q  + (size_t)pt*DT + col);
            k0f[j] = *(const uint32_t*)(g_kf + (size_t)gi0*DT + col);
            k1f[j] = *(const uint32_t*)(g_kf + (size_t)gi1*DT + col);
        }

        float c[16][4];
        uint32_t ahh[8][4];

        #pragma unroll
        for (int j = 0; j < 16; j++) {
            int col = 8*j + t2;
            float2 w0 = *(const float2*)(smf + (MW_D1W>>2) + col);
            float2 w1 = *(const float2*)(smf + (MW_D1W>>2) + DT + col);
            float2 w2 = *(const float2*)(smf + (MW_D1W>>2) + 2*DT + col);
            float2 bb = *(const float2*)(smf + (MW_D1B>>2) + col);
            c[j][0] = fmaxf(bb.x + r0x*w0.x + r0y*w1.x + r0z*w2.x, 0.f);
            c[j][1] = fmaxf(bb.y + r0x*w0.y + r0y*w1.y + r0z*w2.y, 0.f);
            c[j][2] = fmaxf(bb.x + r1x*w0.x + r1y*w1.x + r1z*w2.x, 0.f);
            c[j][3] = fmaxf(bb.y + r1x*w0.y + r1y*w1.y + r1z*w2.y, 0.f);
        }
        cvtA(c, ahh);

        #pragma unroll
        for (int j = 0; j < 16; j++) { c[j][0]=0.f; c[j][1]=0.f; c[j][2]=0.f; c[j][3]=0.f; }
        wgemm(c, ahh, wh0, tr, th);
        uint32_t peb0[16], peb1[16];
        #pragma unroll
        for (int j = 0; j < 16; j++) {
            float2 bb = *(const float2*)(smf + (MW_D2B>>2) + 8*j + t2);
            peb0[j] = cvt2(c[j][0] + bb.x, c[j][1] + bb.y);
            peb1[j] = cvt2(c[j][2] + bb.x, c[j][3] + bb.y);
        }

        #pragma unroll
        for (int j = 0; j < 16; j++) {
            float2 p0 = unp2(peb0[j]), p1 = unp2(peb1[j]);
            float2 qv = unp2(qf[j]);
            float2 k0 = unp2(k0f[j]);
            float2 k1 = unp2(k1f[j]);
            c[j][0] = qv.x - k0.x + p0.x;
            c[j][1] = qv.y - k0.y + p0.y;
            c[j][2] = qv.x - k1.x + p1.x;
            c[j][3] = qv.y - k1.y + p1.y;
        }
        cvtA(c, ahh);

        uint32_t v0f[16], v1f[16];
        #pragma unroll
        for (int j = 0; j < 16; j++) {
            int col = 8*j + t2;
            v0f[j] = *(const uint32_t*)(g_vf + (size_t)gi0*DT + col);
            v1f[j] = *(const uint32_t*)(g_vf + (size_t)gi1*DT + col);
        }

        #pragma unroll
        for (int j = 0; j < 16; j++) { c[j][0]=0.f; c[j][1]=0.f; c[j][2]=0.f; c[j][3]=0.f; }
        wgemm(c, ahh, wh1, tr, th);
        #pragma unroll
        for (int j = 0; j < 16; j++) {
            float2 bb = *(const float2*)(smf + (MW_G1B>>2) + 8*j + t2);
            c[j][0] = fmaxf(c[j][0] + bb.x, 0.f); c[j][1] = fmaxf(c[j][1] + bb.y, 0.f);
            c[j][2] = fmaxf(c[j][2] + bb.x, 0.f); c[j][3] = fmaxf(c[j][3] + bb.y, 0.f);
        }
        cvtA(c, ahh);

        #pragma unroll
        for (int j = 0; j < 16; j++) { c[j][0]=0.f; c[j][1]=0.f; c[j][2]=0.f; c[j][3]=0.f; }
        wgemm(c, ahh, wh2, tr, th);

        int npt = pt + nwarps;
        int ngi0 = gi0, ngi1 = gi1;
        if (npt < NPTS) {
            ngi0 = g_knn[npt*KK + g];
            ngi1 = g_knn[npt*KK + g + 8];
        }

        #pragma unroll
        for (int j = 0; j < 16; j++) {
            int col = 8*j + t2;
            float2 bb = *(const float2*)(smf + (MW_G2B>>2) + col);
            float e00 = __expf(c[j][0] + bb.x);
            float e01 = __expf(c[j][1] + bb.y);
            float e10 = __expf(c[j][2] + bb.x);
            float e11 = __expf(c[j][3] + bb.y);
            float s0 = e00 + e10, s1 = e01 + e11;
            #pragma unroll
            for (int o = 4; o <= 16; o <<= 1) {
                s0 += __shfl_xor_sync(0xffffffffu, s0, o);
                s1 += __shfl_xor_sync(0xffffffffu, s1, o);
            }
            float i0 = 1.0f / s0, i1 = 1.0f / s1;
            float a00 = e00*i0, a10 = e10*i0, a01 = e01*i1, a11 = e11*i1;
            if (write_attn) {
                *(float2*)(attn_out + ((size_t)pt*KK + g    )*DT + col) = make_float2(a00, a01);
                *(float2*)(attn_out + ((size_t)pt*KK + g + 8)*DT + col) = make_float2(a10, a11);
            }
            float2 p0 = unp2(peb0[j]), p1 = unp2(peb1[j]);
            float2 v0 = unp2(v0f[j]), v1 = unp2(v1f[j]);
            float t0 = a00*(v0.x + p0.x) + a10*(v1.x + p1.x);
            float t1 = a01*(v0.y + p0.y) + a11*(v1.y + p1.y);
            #pragma unroll
            for (int o = 4; o <= 16; o <<= 1) {
                t0 += __shfl_xor_sync(0xffffffffu, t0, o);
                t1 += __shfl_xor_sync(0xffffffffu, t1, o);
            }
            if (lane < 4) *(float2*)(g_res + (size_t)pt*DT + col) = make_float2(t0, t1);
        }
        gi0 = ngi0; gi1 = ngi1;
    }
}

// =============================== out = res@fc2_w + b + x (tiled) ===============================
__global__ __launch_bounds__(128, 1) void out_kernel(const float* __restrict__ x,
        const float* __restrict__ fc2_w, const float* __restrict__ fc2_b, float* __restrict__ out) {
    __shared__ float ws[DT*DIN];
    __shared__ float rbuf[16*DT];
    int t = threadIdx.x;
    int base = blockIdx.x * 16;
    {
        float4* ws4=(float4*)ws; const float4* w4=(const float4*)fc2_w;
        for (int i=t; i<DT*DIN/4; i+=128) ws4[i]=w4[i];
        const float4* rsrc = (const float4*)(g_res + (size_t)base*DT);
        float4* rb4=(float4*)rbuf;
        for (int i=t; i<16*DT/4; i+=128) rb4[i]=rsrc[i];
    }
    __syncthreads();
    int c4 = (t & 15) * 4;
    int r2 = (t >> 4) * 2;
    float4 bias = *(const float4*)(fc2_b + c4);
    float a0x=bias.x, a0y=bias.y, a0z=bias.z, a0w=bias.w;
    float a1x=bias.x, a1y=bias.y, a1z=bias.z, a1w=bias.w;
    const float* rrow0 = rbuf + r2*DT;
    const float* rrow1 = rbuf + (r2+1)*DT;
    #pragma unroll 4
    for (int i = 0; i < DT; i++) {
        float4 w = *(const float4*)(ws + i*DIN + c4);
        float ra = rrow0[i], rb = rrow1[i];
        a0x += ra*w.x; a0y += ra*w.y; a0z += ra*w.z; a0w += ra*w.w;
        a1x += rb*w.x; a1y += rb*w.y; a1z += rb*w.z; a1w += rb*w.w;
    }
    {
        float4 x0 = *(const float4*)(x + (size_t)(base+r2)*DIN + c4);
        float4 x1 = *(const float4*)(x + (size_t)(base+r2+1)*DIN + c4);
        *(float4*)(out + (size_t)(base+r2)*DIN + c4)   = make_float4(a0x+x0.x, a0y+x0.y, a0z+x0.z, a0w+x0.w);
        *(float4*)(out + (size_t)(base+r2+1)*DIN + c4) = make_float4(a1x+x1.x, a1y+x1.y, a1z+x1.z, a1w+x1.w);
    }
}

// =============================== launch ===============================
extern "C" void kernel_launch(void* const* d_in, const int* in_sizes, int n_in,
                              void* d_out, int out_size) {
    const float* x     = (const float*)d_in[0];
    const float* pos   = (const float*)d_in[1];
    const float* fc1_w = (const float*)d_in[2];
    const float* fc1_b = (const float*)d_in[3];
    const float* fc2_w = (const float*)d_in[4];
    const float* fc2_b = (const float*)d_in[5];
    const float* d1_w  = (const float*)d_in[6];
    const float* d1_b  = (const float*)d_in[7];
    const float* d2_w  = (const float*)d_in[8];
    const float* d2_b  = (const float*)d_in[9];
    const float* g1_w  = (const float*)d_in[10];
    const float* g1_b  = (const float*)d_in[11];
    const float* g2_w  = (const float*)d_in[12];
    const float* g2_b  = (const float*)d_in[13];
    const float* wq    = (const float*)d_in[14];
    const float* wk    = (const float*)d_in[15];
    const float* wv    = (const float*)d_in[16];
    float* out = (float*)d_out;
    int write_attn = (out_size >= NPTS*DIN + NPTS*KK*DT) ? 1 : 0;
    float* attn_out = out + (size_t)NPTS*DIN;

    int knn_smem = NN*16 + 64*32*8;
    cudaFuncSetAttribute(knn_kernel,       cudaFuncAttributeMaxDynamicSharedMemorySize, knn_smem);
    cudaFuncSetAttribute(qkv_mma_kernel,   cudaFuncAttributeMaxDynamicSharedMemorySize, QS_TOTAL);
    cudaFuncSetAttribute(mega_warp_kernel, cudaFuncAttributeMaxDynamicSharedMemorySize, MW_TOTAL);

    knn_kernel<<<BB*64, 128, knn_smem>>>(pos);
    wprep_kernel<<<7, 256>>>(d2_w, g1_w, g2_w, wq, wk, wv, fc1_w);
    qkv_mma_kernel<<<NPTS/64, 512, QS_TOTAL>>>(x, fc1_b);
    mega_warp_kernel<<<148, 256, MW_TOTAL>>>(pos, d1_w, d1_b, d2_b, g1_b, g2_b,
                                             attn_out, write_attn);
    out_kernel<<<NPTS/16, 128>>>(x, fc2_w, fc2_b, out);
}